// round 1
// baseline (speedup 1.0000x reference)
#include <cuda_runtime.h>
#include <math.h>

// ---------------- problem constants ----------------
#define BB      4
#define NH      16
#define NKV     4
#define HDIM    128
#define DMODEL  2048
#define SQV     1024
#define SQA     64
#define SCACHE  256
#define STOT    1344          // SCACHE + SQV + SQA
#define NQROWS  (BB*NH*SQA)   // 4096 action query rows

// ---------------- device scratch (allowed: __device__ globals) ----------------
__device__ float g_K[BB*NKV*STOT*HDIM];        // unified keys   [b][kv][s][d]
__device__ float g_V[BB*NKV*STOT*HDIM];        // unified values [b][kv][s][d]
__device__ float g_q[BB*NH*SQA*HDIM];          // action queries [b][h][s][d]
__device__ float g_scores[NQROWS*STOT];        // attention probs scratch
__device__ float g_attn[BB*SQA*NH*HDIM];       // attention out  [(b*64+s)][h*128+d]

// ---------------- output index mapping for GEMM epilogues ----------------
// map 0: plain row-major r*N+c
// map 1: kv-vlm   rows r=b*1024+s, cols c=kv*128+d  -> g_K/g_V at seq offset 256
// map 2: kv-act   rows r=b*64+s,   cols c=kv*128+d  -> g_K/g_V at seq offset 1280
// map 3: q-act    rows r=b*64+s,   cols c=h*128+d   -> g_q
__device__ __forceinline__ int out_index(int map, int r, int c, int N) {
    switch (map) {
        case 1: { int b=r>>10, s=r&1023, kv=c>>7, d=c&127;
                  return (((b*NKV+kv)*STOT) + SCACHE + s)*HDIM + d; }
        case 2: { int b=r>>6, s=r&63, kv=c>>7, d=c&127;
                  return (((b*NKV+kv)*STOT) + (SCACHE+SQV) + s)*HDIM + d; }
        case 3: { int b=r>>6, s=r&63, h=c>>7, d=c&127;
                  return (((b*NH+h)*SQA) + s)*HDIM + d; }
        default: return r*N + c;
    }
}

// ---------------- fp32 SGEMM: C = A(MxK) @ W(KxN), 128x128x8 tile, 8x8 microtile ----------------
// dest: 0 -> g_K, 1 -> g_V, 2 -> g_q, 3 -> Cext.  asrc: 1 -> A = g_attn.
__global__ __launch_bounds__(256) void sgemm_kernel(
    const float* __restrict__ Aext, const float* __restrict__ W,
    float* Cext, int M, int N, int K, int map, int dest, int asrc)
{
    __shared__ float As[128][8];
    __shared__ float Bs[8][128];

    const float* A = asrc ? g_attn : Aext;
    int tid = threadIdx.x;
    int tx = tid & 15, ty = tid >> 4;
    int m0 = blockIdx.y * 128, n0 = blockIdx.x * 128;

    float acc[8][8];
#pragma unroll
    for (int i = 0; i < 8; i++)
#pragma unroll
        for (int j = 0; j < 8; j++) acc[i][j] = 0.f;

    int ar = tid >> 1, ac = (tid & 1) * 4;     // A tile: 128 rows x 8 cols
    int br = tid >> 5, bc = (tid & 31) * 4;    // B tile: 8 rows x 128 cols

    for (int k0 = 0; k0 < K; k0 += 8) {
        float4 av = *(const float4*)&A[(size_t)(m0 + ar) * K + k0 + ac];
        float4 bv = *(const float4*)&W[(size_t)(k0 + br) * N + n0 + bc];
        *(float4*)&As[ar][ac] = av;
        *(float4*)&Bs[br][bc] = bv;
        __syncthreads();
#pragma unroll
        for (int kk = 0; kk < 8; kk++) {
            float a[8], b[8];
#pragma unroll
            for (int i = 0; i < 8; i++) a[i] = As[ty*8 + i][kk];
            float4 b0 = *(const float4*)&Bs[kk][tx*8];
            float4 b1 = *(const float4*)&Bs[kk][tx*8 + 4];
            b[0]=b0.x; b[1]=b0.y; b[2]=b0.z; b[3]=b0.w;
            b[4]=b1.x; b[5]=b1.y; b[6]=b1.z; b[7]=b1.w;
#pragma unroll
            for (int i = 0; i < 8; i++)
#pragma unroll
                for (int j = 0; j < 8; j++)
                    acc[i][j] += a[i] * b[j];
        }
        __syncthreads();
    }

    float* C = (dest == 0) ? g_K : (dest == 1) ? g_V : (dest == 2) ? g_q : Cext;
#pragma unroll
    for (int i = 0; i < 8; i++) {
        int r = m0 + ty*8 + i;
#pragma unroll
        for (int j = 0; j < 8; j++) {
            int c = n0 + tx*8 + j;
            C[out_index(map, r, c, N)] = acc[i][j];
        }
    }
}

// ---------------- copy KV cache into unified K/V (seq [0,256)) ----------------
__global__ void copy_cache_kernel(const float* __restrict__ kc, const float* __restrict__ vc)
{
    const int n = BB*NKV*SCACHE*HDIM;  // 524288
    for (int i = blockIdx.x*blockDim.x + threadIdx.x; i < n; i += gridDim.x*blockDim.x) {
        int d  = i & 127;
        int s  = (i >> 7) & 255;
        int bk = i >> 15;                         // b*NKV + kv
        int dst = (bk*STOT + s)*HDIM + d;
        g_K[dst] = kc[i];
        g_V[dst] = vc[i];
    }
}

// ---------------- RoPE (in place), fast-math-safe range reduction ----------------
// which: 0 -> g_K (stot=1344), 1 -> g_q (stot=64)
__global__ void rope_kernel(int which, const int* __restrict__ pos,
                            int nh, int seqlen, int s_off, int total)
{
    int idx = blockIdx.x*blockDim.x + threadIdx.x;
    if (idx >= total) return;
    int i = idx & 63;
    int rest = idx >> 6;
    int s = rest % seqlen; rest /= seqlen;
    int hh = rest % nh;
    int b  = rest / nh;

    float* X = (which == 0) ? g_K : g_q;
    int stot = (which == 0) ? STOT : SQA;

    int p = pos[b*seqlen + s];
    // inv_freq = 10000^(-i/64); log2(10000)/64 = 0.20762050593046868
    float inv = exp2f(-0.20762050593046868f * (float)i);
    float ang = (float)p * inv;                       // fp32 round like reference
    double ad  = (double)ang;
    double red = ad - rint(ad * 0.15915494309189535) * 6.283185307179586;
    float c  = cosf((float)red);
    float sn = sinf((float)red);

    size_t base = ((size_t)((b*nh + hh)*stot + s_off + s)) * HDIM;
    float x1 = X[base + i], x2 = X[base + 64 + i];
    X[base + i]      = x1*c - x2*sn;
    X[base + 64 + i] = x2*c + x1*sn;
}

// ---------------- scores = softcap(QK^T/sqrt(d)) + mask ----------------
// grid: (21 s-tiles of 64, 64 bh), block 256.  C tile: 64q x 64s, 4x4 microtile.
__global__ __launch_bounds__(256) void score_kernel(const float* __restrict__ mask)
{
    __shared__ float Qs[16][65];
    __shared__ float Ks[16][65];

    int bh = blockIdx.y;
    int b = bh >> 4, h = bh & 15, kv = h >> 2;
    int s0 = blockIdx.x * 64;

    const float* Q  = g_q + (size_t)bh * SQA * HDIM;
    const float* Kp = g_K + (size_t)(b*NKV + kv) * STOT * HDIM;

    int tid = threadIdx.x;
    int tx = tid & 15, ty = tid >> 4;
    int row = tid >> 2, c4 = (tid & 3) * 4;

    float acc[4][4];
#pragma unroll
    for (int i = 0; i < 4; i++)
#pragma unroll
        for (int j = 0; j < 4; j++) acc[i][j] = 0.f;

    for (int d0 = 0; d0 < HDIM; d0 += 16) {
        float4 qv = *(const float4*)&Q[row*HDIM + d0 + c4];
        float4 kk4 = *(const float4*)&Kp[(size_t)(s0 + row)*HDIM + d0 + c4];
        Qs[c4+0][row]=qv.x;  Qs[c4+1][row]=qv.y;  Qs[c4+2][row]=qv.z;  Qs[c4+3][row]=qv.w;
        Ks[c4+0][row]=kk4.x; Ks[c4+1][row]=kk4.y; Ks[c4+2][row]=kk4.z; Ks[c4+3][row]=kk4.w;
        __syncthreads();
#pragma unroll
        for (int kk = 0; kk < 16; kk++) {
            float a[4], bb[4];
#pragma unroll
            for (int i = 0; i < 4; i++) a[i]  = Qs[kk][ty*4 + i];
#pragma unroll
            for (int j = 0; j < 4; j++) bb[j] = Ks[kk][tx*4 + j];
#pragma unroll
            for (int i = 0; i < 4; i++)
#pragma unroll
                for (int j = 0; j < 4; j++)
                    acc[i][j] += a[i] * bb[j];
        }
        __syncthreads();
    }

    const float scale = 0.08838834764831845f;  // 1/sqrt(128)
#pragma unroll
    for (int i = 0; i < 4; i++) {
        int q = ty*4 + i;
#pragma unroll
        for (int j = 0; j < 4; j++) {
            int s = s0 + tx*4 + j;
            float v = acc[i][j] * scale;
            v = tanhf(v * 0.02f) * 50.0f
              + mask[(size_t)b*(1088*1344) + (size_t)(1024 + q)*1344 + s];
            g_scores[(size_t)(bh*SQA + q)*STOT + s] = v;
        }
    }
}

// ---------------- row softmax, 1 warp per row (1344 = 42*32) ----------------
__global__ void softmax_kernel()
{
    int row  = blockIdx.x*4 + (threadIdx.x >> 5);   // 0..4095
    int lane = threadIdx.x & 31;
    float* p = g_scores + (size_t)row * STOT;

    float vals[42];
    float m = -1e30f;
#pragma unroll
    for (int i = 0; i < 42; i++) { vals[i] = p[i*32 + lane]; m = fmaxf(m, vals[i]); }
#pragma unroll
    for (int off = 16; off > 0; off >>= 1) m = fmaxf(m, __shfl_xor_sync(0xffffffffu, m, off));
    float sum = 0.f;
#pragma unroll
    for (int i = 0; i < 42; i++) { vals[i] = __expf(vals[i] - m); sum += vals[i]; }
#pragma unroll
    for (int off = 16; off > 0; off >>= 1) sum += __shfl_xor_sync(0xffffffffu, sum, off);
    float invs = 1.0f / sum;
#pragma unroll
    for (int i = 0; i < 42; i++) p[i*32 + lane] = vals[i] * invs;
}

// ---------------- out = P @ V, block per (b,h), 64q x 128d ----------------
__global__ __launch_bounds__(256) void pv_kernel()
{
    __shared__ float Vs[32][128];
    __shared__ float Ws[64][36];

    int bh = blockIdx.x;
    int b = bh >> 4, h = bh & 15, kv = h >> 2;
    const float* Vp = g_V + (size_t)(b*NKV + kv) * STOT * HDIM;
    const float* Wp = g_scores + (size_t)bh * SQA * STOT;

    int tid = threadIdx.x;
    int tx = tid & 31, ty = tid >> 5;      // tx: d/4 group, ty: q/8 group

    float acc[8][4];
#pragma unroll
    for (int i = 0; i < 8; i++)
#pragma unroll
        for (int j = 0; j < 4; j++) acc[i][j] = 0.f;

    int wq = tid >> 2, wc = (tid & 3) * 8;  // score tile load coords

    for (int k0 = 0; k0 < STOT; k0 += 32) {
        // V tile 32x128
#pragma unroll
        for (int it = 0; it < 4; it++) {
            int idx = tid + it*256;
            int r = idx >> 5, cc = (idx & 31) * 4;
            *(float4*)&Vs[r][cc] = *(const float4*)&Vp[(size_t)(k0 + r)*HDIM + cc];
        }
        // P tile 64x32
        *(float4*)&Ws[wq][wc]     = *(const float4*)&Wp[(size_t)wq*STOT + k0 + wc];
        *(float4*)&Ws[wq][wc + 4] = *(const float4*)&Wp[(size_t)wq*STOT + k0 + wc + 4];
        __syncthreads();
#pragma unroll
        for (int kk = 0; kk < 32; kk++) {
            float4 v4 = *(const float4*)&Vs[kk][tx*4];
#pragma unroll
            for (int i = 0; i < 8; i++) {
                float w = Ws[ty*8 + i][kk];
                acc[i][0] += w * v4.x;
                acc[i][1] += w * v4.y;
                acc[i][2] += w * v4.z;
                acc[i][3] += w * v4.w;
            }
        }
        __syncthreads();
    }

#pragma unroll
    for (int i = 0; i < 8; i++) {
        int q = ty*8 + i;
        float4 o = make_float4(acc[i][0], acc[i][1], acc[i][2], acc[i][3]);
        *(float4*)&g_attn[(size_t)(b*SQA + q)*(NH*HDIM) + h*HDIM + tx*4] = o;
    }
}

// ---------------- launch ----------------
extern "C" void kernel_launch(void* const* d_in, const int* in_sizes, int n_in,
                              void* d_out, int out_size)
{
    (void)in_sizes; (void)n_in; (void)out_size;
    const float* mask    = (const float*)d_in[0];
    const int*   pos_vlm = (const int*)  d_in[1];
    const int*   pos_act = (const int*)  d_in[2];
    const float* h_vlm   = (const float*)d_in[3];
    const float* h_act   = (const float*)d_in[4];
    const float* k_cache = (const float*)d_in[5];
    const float* v_cache = (const float*)d_in[6];
    // d_in[7] = Wq_vlm: provably unused (q_vlm rows are discarded by reference)
    const float* Wk_vlm  = (const float*)d_in[8];
    const float* Wv_vlm  = (const float*)d_in[9];
    const float* Wq_act  = (const float*)d_in[10];
    const float* Wk_act  = (const float*)d_in[11];
    const float* Wv_act  = (const float*)d_in[12];
    const float* Wo_act  = (const float*)d_in[13];
    float* out = (float*)d_out;

    // cache -> unified K/V
    copy_cache_kernel<<<512, 256>>>(k_cache, v_cache);

    // projections (fused scatter epilogues into attention layouts)
    sgemm_kernel<<<dim3(4, 32), 256>>>(h_vlm, Wk_vlm, nullptr, 4096,  512, 2048, 1, 0, 0);
    sgemm_kernel<<<dim3(4, 32), 256>>>(h_vlm, Wv_vlm, nullptr, 4096,  512, 2048, 1, 1, 0);
    sgemm_kernel<<<dim3(16, 2), 256>>>(h_act, Wq_act, nullptr,  256, 2048, 2048, 3, 2, 0);
    sgemm_kernel<<<dim3(4, 2),  256>>>(h_act, Wk_act, nullptr,  256,  512, 2048, 2, 0, 0);
    sgemm_kernel<<<dim3(4, 2),  256>>>(h_act, Wv_act, nullptr,  256,  512, 2048, 2, 1, 0);

    // RoPE (k_vlm, k_act, q_act) — cache keys are NOT roped (matches reference)
    {
        int tot = BB*NKV*SQV*64;
        rope_kernel<<<(tot + 255)/256, 256>>>(0, pos_vlm, NKV, SQV, SCACHE, tot);
    }
    {
        int tot = BB*NKV*SQA*64;
        rope_kernel<<<(tot + 255)/256, 256>>>(0, pos_act, NKV, SQA, SCACHE + SQV, tot);
    }
    {
        int tot = BB*NH*SQA*64;
        rope_kernel<<<(tot + 255)/256, 256>>>(1, pos_act, NH, SQA, 0, tot);
    }

    // attention (action queries only)
    score_kernel<<<dim3(21, 64), 256>>>(mask);
    softmax_kernel<<<1024, 128>>>();
    pv_kernel<<<64, 256>>>();

    // output projection: (256 x 2048) @ Wo_act -> d_out
    sgemm_kernel<<<dim3(16, 2), 256>>>(nullptr, Wo_act, out, 256, 2048, 2048, 0, 3, 1);
}

// round 2
// speedup vs baseline: 2.6721x; 2.6721x over previous
#include <cuda_runtime.h>
#include <math.h>

// ---------------- problem constants ----------------
#define BB      4
#define NH      16
#define NKV     4
#define HDIM    128
#define DMODEL  2048
#define SQV     1024
#define SQA     64
#define SCACHE  256
#define STOT    1344          // SCACHE + SQV + SQA
#define NQROWS  (BB*NH*SQA)   // 4096 action query rows

// ---------------- device scratch ----------------
__device__ float g_K[BB*NKV*STOT*HDIM];        // unified keys   [b][kv][s][d]
__device__ float g_V[BB*NKV*STOT*HDIM];        // unified values [b][kv][s][d]
__device__ float g_q[BB*NH*SQA*HDIM];          // action queries [b][h][s][d]
__device__ float g_scores[NQROWS*STOT];        // attention probs scratch
__device__ float g_attn[BB*SQA*NH*HDIM];       // attention out  [(b*64+s)][h*128+d]

// ---------------- zero-init all atomic-accumulated buffers ----------------
__global__ void zero_kernel(float* out)
{
    int tid = blockIdx.x*blockDim.x + threadIdx.x;
    int stride = gridDim.x*blockDim.x;
    const int nK = BB*NKV*STOT*HDIM;       // 2752512
    const int nq = BB*NH*SQA*HDIM;         // 524288
    const int na = BB*SQA*NH*HDIM;         // 524288
    const int no = BB*SQA*DMODEL;          // 524288
    for (int i = tid; i < nK; i += stride) { g_K[i] = 0.f; g_V[i] = 0.f; }
    for (int i = tid; i < nq; i += stride) g_q[i] = 0.f;
    for (int i = tid; i < na; i += stride) g_attn[i] = 0.f;
    for (int i = tid; i < no; i += stride) out[i] = 0.f;
}

// ---------------- output index mapping for GEMM epilogues ----------------
// map 0: plain row-major r*N+c
// map 1: kv-vlm   rows r=b*1024+s, cols c=kv*128+d  -> seq offset 256
// map 2: kv-act   rows r=b*64+s,   cols c=kv*128+d  -> seq offset 1280
// map 3: q-act    rows r=b*64+s,   cols c=h*128+d   -> g_q
__device__ __forceinline__ int out_index(int map, int r, int c, int N) {
    switch (map) {
        case 1: { int b=r>>10, s=r&1023, kv=c>>7, d=c&127;
                  return (((b*NKV+kv)*STOT) + SCACHE + s)*HDIM + d; }
        case 2: { int b=r>>6, s=r&63, kv=c>>7, d=c&127;
                  return (((b*NKV+kv)*STOT) + (SCACHE+SQV) + s)*HDIM + d; }
        case 3: { int b=r>>6, s=r&63, h=c>>7, d=c&127;
                  return (((b*NH+h)*SQA) + s)*HDIM + d; }
        default: return r*N + c;
    }
}

// ---------------- fp32 SGEMM with split-K: 128x128 tile, 8x8 microtile ----------------
// dest: 0 -> g_K, 1 -> g_V, 2 -> g_q, 3 -> Cext.  asrc: 1 -> A = g_attn.
// blockIdx.z selects K-slab of length klen; gridDim.z>1 => atomicAdd epilogue.
__global__ __launch_bounds__(256) void sgemm_kernel(
    const float* __restrict__ Aext, const float* __restrict__ W,
    float* Cext, int M, int N, int K, int map, int dest, int asrc, int klen)
{
    __shared__ float As[128][8];
    __shared__ float Bs[8][128];

    const float* A = asrc ? g_attn : Aext;
    int tid = threadIdx.x;
    int tx = tid & 15, ty = tid >> 4;
    int m0 = blockIdx.y * 128, n0 = blockIdx.x * 128;
    int kstart = blockIdx.z * klen;
    int kend   = kstart + klen;

    float acc[8][8];
#pragma unroll
    for (int i = 0; i < 8; i++)
#pragma unroll
        for (int j = 0; j < 8; j++) acc[i][j] = 0.f;

    int ar = tid >> 1, ac = (tid & 1) * 4;     // A tile: 128 rows x 8 cols
    int br = tid >> 5, bc = (tid & 31) * 4;    // B tile: 8 rows x 128 cols

    // register-prefetch pipeline over K slabs of 8
    float4 av = *(const float4*)&A[(size_t)(m0 + ar) * K + kstart + ac];
    float4 bv = *(const float4*)&W[(size_t)(kstart + br) * N + n0 + bc];

    for (int k0 = kstart; k0 < kend; k0 += 8) {
        *(float4*)&As[ar][ac] = av;
        *(float4*)&Bs[br][bc] = bv;
        __syncthreads();
        if (k0 + 8 < kend) {
            av = *(const float4*)&A[(size_t)(m0 + ar) * K + k0 + 8 + ac];
            bv = *(const float4*)&W[(size_t)(k0 + 8 + br) * N + n0 + bc];
        }
#pragma unroll
        for (int kk = 0; kk < 8; kk++) {
            float a[8], b[8];
#pragma unroll
            for (int i = 0; i < 8; i++) a[i] = As[ty*8 + i][kk];
            float4 b0 = *(const float4*)&Bs[kk][tx*8];
            float4 b1 = *(const float4*)&Bs[kk][tx*8 + 4];
            b[0]=b0.x; b[1]=b0.y; b[2]=b0.z; b[3]=b0.w;
            b[4]=b1.x; b[5]=b1.y; b[6]=b1.z; b[7]=b1.w;
#pragma unroll
            for (int i = 0; i < 8; i++)
#pragma unroll
                for (int j = 0; j < 8; j++)
                    acc[i][j] += a[i] * b[j];
        }
        __syncthreads();
    }

    float* C = (dest == 0) ? g_K : (dest == 1) ? g_V : (dest == 2) ? g_q : Cext;
    bool split = (gridDim.z > 1);
#pragma unroll
    for (int i = 0; i < 8; i++) {
        int r = m0 + ty*8 + i;
#pragma unroll
        for (int j = 0; j < 8; j++) {
            int c = n0 + tx*8 + j;
            int idx = out_index(map, r, c, N);
            if (split) atomicAdd(&C[idx], acc[i][j]);
            else       C[idx] = acc[i][j];
        }
    }
}

// ---------------- copy KV cache into unified K/V (seq [0,256)) ----------------
__global__ void copy_cache_kernel(const float* __restrict__ kc, const float* __restrict__ vc)
{
    const int n = BB*NKV*SCACHE*HDIM;  // 524288
    for (int i = blockIdx.x*blockDim.x + threadIdx.x; i < n; i += gridDim.x*blockDim.x) {
        int d  = i & 127;
        int s  = (i >> 7) & 255;
        int bk = i >> 15;                         // b*NKV + kv
        int dst = (bk*STOT + s)*HDIM + d;
        g_K[dst] = kc[i];
        g_V[dst] = vc[i];
    }
}

// ---------------- RoPE (in place), fast-math-safe range reduction ----------------
// which: 0 -> g_K (stot=1344), 1 -> g_q (stot=64)
__global__ void rope_kernel(int which, const int* __restrict__ pos,
                            int nh, int seqlen, int s_off, int total)
{
    int idx = blockIdx.x*blockDim.x + threadIdx.x;
    if (idx >= total) return;
    int i = idx & 63;
    int rest = idx >> 6;
    int s = rest % seqlen; rest /= seqlen;
    int hh = rest % nh;
    int b  = rest / nh;

    float* X = (which == 0) ? g_K : g_q;
    int stot = (which == 0) ? STOT : SQA;

    int p = pos[b*seqlen + s];
    float inv = exp2f(-0.20762050593046868f * (float)i);   // 10000^(-i/64)
    float ang = (float)p * inv;                            // fp32 round like reference
    double ad  = (double)ang;
    double red = ad - rint(ad * 0.15915494309189535) * 6.283185307179586;
    float c  = cosf((float)red);
    float sn = sinf((float)red);

    size_t base = ((size_t)((b*nh + hh)*stot + s_off + s)) * HDIM;
    float x1 = X[base + i], x2 = X[base + 64 + i];
    X[base + i]      = x1*c - x2*sn;
    X[base + 64 + i] = x2*c + x1*sn;
}

// ---------------- scores = softcap(QK^T/sqrt(d)) + mask ----------------
__global__ __launch_bounds__(256) void score_kernel(const float* __restrict__ mask)
{
    __shared__ float Qs[16][65];
    __shared__ float Ks[16][65];

    int bh = blockIdx.y;
    int b = bh >> 4, h = bh & 15, kv = h >> 2;
    int s0 = blockIdx.x * 64;

    const float* Q  = g_q + (size_t)bh * SQA * HDIM;
    const float* Kp = g_K + (size_t)(b*NKV + kv) * STOT * HDIM;

    int tid = threadIdx.x;
    int tx = tid & 15, ty = tid >> 4;
    int row = tid >> 2, c4 = (tid & 3) * 4;

    float acc[4][4];
#pragma unroll
    for (int i = 0; i < 4; i++)
#pragma unroll
        for (int j = 0; j < 4; j++) acc[i][j] = 0.f;

    for (int d0 = 0; d0 < HDIM; d0 += 16) {
        float4 qv = *(const float4*)&Q[row*HDIM + d0 + c4];
        float4 kk4 = *(const float4*)&Kp[(size_t)(s0 + row)*HDIM + d0 + c4];
        Qs[c4+0][row]=qv.x;  Qs[c4+1][row]=qv.y;  Qs[c4+2][row]=qv.z;  Qs[c4+3][row]=qv.w;
        Ks[c4+0][row]=kk4.x; Ks[c4+1][row]=kk4.y; Ks[c4+2][row]=kk4.z; Ks[c4+3][row]=kk4.w;
        __syncthreads();
#pragma unroll
        for (int kk = 0; kk < 16; kk++) {
            float a[4], bb[4];
#pragma unroll
            for (int i = 0; i < 4; i++) a[i]  = Qs[kk][ty*4 + i];
#pragma unroll
            for (int j = 0; j < 4; j++) bb[j] = Ks[kk][tx*4 + j];
#pragma unroll
            for (int i = 0; i < 4; i++)
#pragma unroll
                for (int j = 0; j < 4; j++)
                    acc[i][j] += a[i] * bb[j];
        }
        __syncthreads();
    }

    const float scale = 0.08838834764831845f;  // 1/sqrt(128)
#pragma unroll
    for (int i = 0; i < 4; i++) {
        int q = ty*4 + i;
#pragma unroll
        for (int j = 0; j < 4; j++) {
            int s = s0 + tx*4 + j;
            float v = acc[i][j] * scale;
            v = tanhf(v * 0.02f) * 50.0f
              + mask[(size_t)b*(1088*1344) + (size_t)(1024 + q)*1344 + s];
            g_scores[(size_t)(bh*SQA + q)*STOT + s] = v;
        }
    }
}

// ---------------- row softmax, 1 warp per row (1344 = 42*32) ----------------
__global__ void softmax_kernel()
{
    int row  = blockIdx.x*4 + (threadIdx.x >> 5);   // 0..4095
    int lane = threadIdx.x & 31;
    float* p = g_scores + (size_t)row * STOT;

    float vals[42];
    float m = -1e30f;
#pragma unroll
    for (int i = 0; i < 42; i++) { vals[i] = p[i*32 + lane]; m = fmaxf(m, vals[i]); }
#pragma unroll
    for (int off = 16; off > 0; off >>= 1) m = fmaxf(m, __shfl_xor_sync(0xffffffffu, m, off));
    float sum = 0.f;
#pragma unroll
    for (int i = 0; i < 42; i++) { vals[i] = __expf(vals[i] - m); sum += vals[i]; }
#pragma unroll
    for (int off = 16; off > 0; off >>= 1) sum += __shfl_xor_sync(0xffffffffu, sum, off);
    float invs = 1.0f / sum;
#pragma unroll
    for (int i = 0; i < 42; i++) p[i*32 + lane] = vals[i] * invs;
}

// ---------------- out = P @ V, split over keys: grid (64 bh, 6 k-chunks of 224) ----------------
__global__ __launch_bounds__(256) void pv_kernel()
{
    __shared__ float Vs[32][128];
    __shared__ float Ws[64][36];

    int bh = blockIdx.x;
    int b = bh >> 4, h = bh & 15, kv = h >> 2;
    int kbase = blockIdx.y * 224;
    const float* Vp = g_V + (size_t)(b*NKV + kv) * STOT * HDIM;
    const float* Wp = g_scores + (size_t)bh * SQA * STOT;

    int tid = threadIdx.x;
    int tx = tid & 31, ty = tid >> 5;      // tx: d/4 group, ty: q/8 group

    float acc[8][4];
#pragma unroll
    for (int i = 0; i < 8; i++)
#pragma unroll
        for (int j = 0; j < 4; j++) acc[i][j] = 0.f;

    int wq = tid >> 2, wc = (tid & 3) * 8;  // score tile load coords

    for (int kk0 = 0; kk0 < 224; kk0 += 32) {
        int k0 = kbase + kk0;
#pragma unroll
        for (int it = 0; it < 4; it++) {
            int idx = tid + it*256;
            int r = idx >> 5, cc = (idx & 31) * 4;
            *(float4*)&Vs[r][cc] = *(const float4*)&Vp[(size_t)(k0 + r)*HDIM + cc];
        }
        *(float4*)&Ws[wq][wc]     = *(const float4*)&Wp[(size_t)wq*STOT + k0 + wc];
        *(float4*)&Ws[wq][wc + 4] = *(const float4*)&Wp[(size_t)wq*STOT + k0 + wc + 4];
        __syncthreads();
#pragma unroll
        for (int kk = 0; kk < 32; kk++) {
            float4 v4 = *(const float4*)&Vs[kk][tx*4];
#pragma unroll
            for (int i = 0; i < 8; i++) {
                float w = Ws[ty*8 + i][kk];
                acc[i][0] += w * v4.x;
                acc[i][1] += w * v4.y;
                acc[i][2] += w * v4.z;
                acc[i][3] += w * v4.w;
            }
        }
        __syncthreads();
    }

#pragma unroll
    for (int i = 0; i < 8; i++) {
        int q = ty*8 + i;
        float* dst = &g_attn[(size_t)(b*SQA + q)*(NH*HDIM) + h*HDIM + tx*4];
        atomicAdd(&dst[0], acc[i][0]);
        atomicAdd(&dst[1], acc[i][1]);
        atomicAdd(&dst[2], acc[i][2]);
        atomicAdd(&dst[3], acc[i][3]);
    }
}

// ---------------- launch ----------------
extern "C" void kernel_launch(void* const* d_in, const int* in_sizes, int n_in,
                              void* d_out, int out_size)
{
    (void)in_sizes; (void)n_in; (void)out_size;
    const float* mask    = (const float*)d_in[0];
    const int*   pos_vlm = (const int*)  d_in[1];
    const int*   pos_act = (const int*)  d_in[2];
    const float* h_vlm   = (const float*)d_in[3];
    const float* h_act   = (const float*)d_in[4];
    const float* k_cache = (const float*)d_in[5];
    const float* v_cache = (const float*)d_in[6];
    // d_in[7] = Wq_vlm: unused (q_vlm rows are discarded by reference)
    const float* Wk_vlm  = (const float*)d_in[8];
    const float* Wv_vlm  = (const float*)d_in[9];
    const float* Wq_act  = (const float*)d_in[10];
    const float* Wk_act  = (const float*)d_in[11];
    const float* Wv_act  = (const float*)d_in[12];
    const float* Wo_act  = (const float*)d_in[13];
    float* out = (float*)d_out;

    // zero all atomically-accumulated buffers, then copy cache
    zero_kernel<<<1024, 256>>>(out);
    copy_cache_kernel<<<512, 256>>>(k_cache, v_cache);

    // projections: split-K for full-chip parallelism
    sgemm_kernel<<<dim3(4, 32, 2), 256>>>(h_vlm, Wk_vlm, nullptr, 4096,  512, 2048, 1, 0, 0, 1024);
    sgemm_kernel<<<dim3(4, 32, 2), 256>>>(h_vlm, Wv_vlm, nullptr, 4096,  512, 2048, 1, 1, 0, 1024);
    sgemm_kernel<<<dim3(16, 2, 8), 256>>>(h_act, Wq_act, nullptr,  256, 2048, 2048, 3, 2, 0,  256);
    sgemm_kernel<<<dim3(4, 2, 32), 256>>>(h_act, Wk_act, nullptr,  256,  512, 2048, 2, 0, 0,   64);
    sgemm_kernel<<<dim3(4, 2, 32), 256>>>(h_act, Wv_act, nullptr,  256,  512, 2048, 2, 1, 0,   64);

    // RoPE (k_vlm, k_act, q_act) — cache keys are NOT roped (matches reference)
    {
        int tot = BB*NKV*SQV*64;
        rope_kernel<<<(tot + 255)/256, 256>>>(0, pos_vlm, NKV, SQV, SCACHE, tot);
    }
    {
        int tot = BB*NKV*SQA*64;
        rope_kernel<<<(tot + 255)/256, 256>>>(0, pos_act, NKV, SQA, SCACHE + SQV, tot);
    }
    {
        int tot = BB*NH*SQA*64;
        rope_kernel<<<(tot + 255)/256, 256>>>(1, pos_act, NH, SQA, 0, tot);
    }

    // attention (action queries only)
    score_kernel<<<dim3(21, 64), 256>>>(mask);
    softmax_kernel<<<1024, 128>>>();
    pv_kernel<<<dim3(64, 6), 256>>>();

    // output projection: (256 x 2048) @ Wo_act -> d_out, split-K 8
    sgemm_kernel<<<dim3(16, 2, 8), 256>>>(nullptr, Wo_act, out, 256, 2048, 2048, 0, 3, 1, 256);
}